// round 15
// baseline (speedup 1.0000x reference)
#include <cuda_runtime.h>
#include <math.h>
#include <stdint.h>

#define T_LEN 1000
#define BATCH 32
#define NF 34
#define HDIM 640
#define NB 128            // persistent blocks (5 hidden cols each)

// ------------------------- device scratch ----------------------------------
__device__ float d_X2[BATCH * 2 * NF * T_LEN];           // 8.7 MB
__device__ float d_dkw0[HDIM * 14];
__device__ float d_dkw1[HDIM * 14];
__device__ int   d_dklo[HDIM * 14];
__device__ float d_Y[HDIM * BATCH * T_LEN];              // 81.9 MB  [hseq][b][t]
__device__ double d_p4sum[640];
__device__ double d_p4sq[640];
__device__ float d_mean[64];
__device__ float d_rstd[64];
__device__ float d_seq[(size_t)T_LEN * HDIM * BATCH];    // 81.9 MB  [t][k][b]
__device__ float d_hbuf[2][HDIM * BATCH];                // ping-pong h  [k][b]
__device__ float d_fcpart[(size_t)T_LEN * NB * BATCH];   // 16.4 MB

// ------------------------- grid barrier ------------------------------------
__device__ volatile unsigned g_epoch = 0;
__device__ unsigned g_count = 0;

__device__ __forceinline__ void grid_barrier() {
    __syncthreads();
    if (threadIdx.x == 0) {
        unsigned e = g_epoch;
        __threadfence();
        if (atomicAdd(&g_count, 1u) == NB - 1) {
            g_count = 0;
            __threadfence();
            g_epoch = e + 1;
        } else {
            while (g_epoch == e) { }
        }
        __threadfence();
    }
    __syncthreads();
}

// split arrive/wait: ih matvec runs between them to hide barrier latency
__device__ __forceinline__ unsigned barrier_arrive() {
    unsigned e = 0;
    __syncthreads();
    if (threadIdx.x == 0) {
        e = g_epoch;
        __threadfence();
        if (atomicAdd(&g_count, 1u) == NB - 1) {
            g_count = 0;
            __threadfence();
            g_epoch = e + 1;
        }
    }
    return e;
}
__device__ __forceinline__ void barrier_wait(unsigned e) {
    if (threadIdx.x == 0) {
        while (g_epoch == e) { }
        __threadfence();
    }
    __syncthreads();
}

// ------------------------- f32x2 / cp.async helpers ------------------------
__device__ __forceinline__ unsigned long long ffma2(unsigned long long a,
                                                    unsigned long long b,
                                                    unsigned long long c) {
    unsigned long long d;
    asm("fma.rn.f32x2 %0, %1, %2, %3;" : "=l"(d) : "l"(a), "l"(b), "l"(c));
    return d;
}
__device__ __forceinline__ unsigned long long dup2(float w) {
    unsigned long long d;
    asm("mov.b64 %0, {%1, %1};" : "=l"(d) : "r"(__float_as_uint(w)));
    return d;
}
__device__ __forceinline__ void cp16(uint32_t dst, const void* src) {
    asm volatile("cp.async.cg.shared.global [%0], [%1], 16;" :: "r"(dst), "l"(src));
}
#define CP_COMMIT() asm volatile("cp.async.commit_group;")
#define CP_WAIT(N)  asm volatile("cp.async.wait_group %0;" :: "n"(N))

// ------------------- K1: truncated EMA highpass + rectify ------------------
__global__ void k1_highpass(const float* __restrict__ x,
                            const float* __restrict__ a_vals,
                            const float* __restrict__ w_vals) {
    int b = blockIdx.x, f = blockIdx.y;
    __shared__ float xs[T_LEN];
    __shared__ float cs[200];
    const float* xr = x + (size_t)(b * NF + f) * T_LEN;
    for (int i = threadIdx.x; i < T_LEN; i += 256) xs[i] = xr[i];
    float a = a_vals[f];
    float w = w_vals[f];
    float l2 = log2f(1.0f - a);
    for (int j = threadIdx.x; j < 200; j += 256) cs[j] = a * exp2f(l2 * (float)j);
    __syncthreads();
    for (int t = threadIdx.x; t < T_LEN; t += 256) {
        float low = 0.f;
        int jm = min(199, t);
        for (int j = 0; j <= jm; ++j) low += cs[j] * xs[t - j];
        float hp = xs[t] - w * low;
        d_X2[((size_t)(b * 2 + 0) * NF + f) * T_LEN + t] = fmaxf(hp, 0.f);
        d_X2[((size_t)(b * 2 + 1) * NF + f) * T_LEN + t] = fmaxf(-hp, 0.f);
    }
}

// ------------------- K2: DCLS triangular kernel -> 2 taps ------------------
__global__ void k2_dk(const float* __restrict__ dcls_w,
                      const float* __restrict__ dcls_p) {
    int idx = blockIdx.x * 256 + threadIdx.x;
    if (idx < HDIM * 14) {
        float p = fminf(fmaxf(dcls_p[idx], 0.f), 8.f);
        float lo = floorf(p);
        float fr = p - lo;
        float w = dcls_w[idx];
        d_dkw0[idx] = w * (1.f - fr);
        d_dkw1[idx] = w * fr;
        d_dklo[idx] = (int)lo;
    }
}

// ------------------- K3: DCLS grouped conv + bias --------------------------
__global__ void k3_dcls(const float* __restrict__ dcls_b) {
    int g = blockIdx.x;     // 0..9
    int b = blockIdx.y;     // 0..31
    extern __shared__ float us[];           // 14 * 1012 floats
    const int P = 1012;
    for (int i = threadIdx.x; i < 14 * P; i += 256) us[i] = 0.f;
    __syncthreads();
    for (int i = 0; i < 14; ++i) {
        int s = i / 7, kk = i % 7;
        const float* src = d_X2 + ((size_t)(b * 2 + s) * NF + g * 3 + kk) * T_LEN;
        for (int t = threadIdx.x; t < T_LEN; t += 256) us[i * P + 4 + t] = src[t];
    }
    __syncthreads();
    for (int c = 0; c < 64; ++c) {
        int h = g * 64 + c;
        float w0[14], w1[14]; int lo[14];
#pragma unroll
        for (int i = 0; i < 14; ++i) {
            w0[i] = d_dkw0[h * 14 + i];
            w1[i] = d_dkw1[h * 14 + i];
            lo[i] = d_dklo[h * 14 + i];
        }
        float bias = dcls_b[h];
        int hseq = c * 10 + g;
        float* dst = d_Y + ((size_t)hseq * BATCH + b) * T_LEN;
        for (int t = threadIdx.x; t < T_LEN; t += 256) {
            float acc = bias;
#pragma unroll
            for (int i = 0; i < 14; ++i) {
                acc += w0[i] * us[i * P + t + lo[i]];
                acc += w1[i] * us[i * P + t + lo[i] + 1];
            }
            dst[t] = acc;
        }
    }
}

// ------------------- K4a: BN partial sums (640 blocks, 256 thr) ------------
__global__ void k4a_stats() {
    const int bid = blockIdx.x;
    const float4* p = (const float4*)(d_Y + (size_t)bid * 32000);
    double s0 = 0.0, s1 = 0.0, q0 = 0.0, q1 = 0.0;
    for (int i = threadIdx.x; i < 8000; i += 512) {
        float4 v = p[i];
        s0 += (double)v.x + (double)v.y;
        s1 += (double)v.z + (double)v.w;
        q0 += (double)v.x * v.x + (double)v.y * v.y;
        q1 += (double)v.z * v.z + (double)v.w * v.w;
        int i2 = i + 256;
        if (i2 < 8000) {
            float4 u = p[i2];
            s0 += (double)u.x + (double)u.y;
            s1 += (double)u.z + (double)u.w;
            q0 += (double)u.x * u.x + (double)u.y * u.y;
            q1 += (double)u.z * u.z + (double)u.w * u.w;
        }
    }
    double s = s0 + s1, s2 = q0 + q1;
    __shared__ double sh[256], sh2[256];
    sh[threadIdx.x] = s; sh2[threadIdx.x] = s2;
    __syncthreads();
    for (int o = 128; o > 0; o >>= 1) {
        if (threadIdx.x < o) { sh[threadIdx.x] += sh[threadIdx.x + o]; sh2[threadIdx.x] += sh2[threadIdx.x + o]; }
        __syncthreads();
    }
    if (threadIdx.x == 0) { d_p4sum[bid] = sh[0]; d_p4sq[bid] = sh2[0]; }
}

// ------------------- K4b: combine -> mean/rstd -----------------------------
__global__ void k4b_stats() {
    int c = threadIdx.x;                    // 64 threads
    double s = 0.0, s2 = 0.0;
#pragma unroll
    for (int j = 0; j < 10; ++j) { s += d_p4sum[c * 10 + j]; s2 += d_p4sq[c * 10 + j]; }
    double mean = s / 320000.0;
    double var = s2 / 320000.0 - mean * mean;
    d_mean[c] = (float)mean;
    d_rstd[c] = (float)(1.0 / sqrt(var + 1e-5));
}

// ------------------- K5: normalize + sigmoid -> seq[t][k][b] ---------------
__global__ void k5_norm(const float* __restrict__ gamma,
                        const float* __restrict__ beta) {
    int h = blockIdx.x;
    int c = h / 10;
    float m = d_mean[c], r = d_rstd[c], ga = gamma[c], be = beta[c];
    const float* src = d_Y + (size_t)h * BATCH * T_LEN;
    __shared__ float ts[32][257];
    for (int t0 = 0; t0 < T_LEN; t0 += 256) {
        __syncthreads();
        for (int i = threadIdx.x; i < 32 * 256; i += 256) {
            int b = i >> 8, tl = i & 255;
            if (t0 + tl < T_LEN) ts[b][tl] = src[(size_t)b * T_LEN + t0 + tl];
        }
        __syncthreads();
        int b2 = threadIdx.x & 31, tl2 = threadIdx.x >> 5;
        for (int tt = tl2; tt < 256 && t0 + tt < T_LEN; tt += 8) {
            float v = (ts[b2][tt] - m) * r * ga + be;
            float sg = 1.f / (1.f + expf(-v));
            d_seq[(size_t)(t0 + tt) * (HDIM * BATCH) + h * BATCH + b2] = sg;
        }
    }
}

// ------------------- K6: persistent GRU, pipelined staging -----------------
// Thread tile per matvec: 4 rows x 8 batches, 16-way split-k.
// warp w: rg = w&3 (rows 4rg..+3), kh = w>>2 (0..1)
// lane l: bg = l&3 (batches 8bg..+7), kq = l>>2 (0..7); ks = kh*8+kq
// SMEM (floats): sbuf[640*32] | hb[2][160*32] | wih[640*16] | whh[640*16]
//                xacc[2*16*32] | gacc[2*16*32] | hn[5*32] | bih[16] | bhh[16] | fcw[8]
#define SM_SBUF 0
#define SM_HB   (SM_SBUF + HDIM * BATCH)        // 20480
#define SM_WIH  (SM_HB + 2 * 160 * 32)          // +10240
#define SM_WHH  (SM_WIH + HDIM * 16)            // +10240
#define SM_XACC (SM_WHH + HDIM * 16)            // +10240
#define SM_GACC (SM_XACC + 2 * 16 * 32)         // +1024
#define SM_HN   (SM_GACC + 2 * 16 * 32)         // +1024
#define SM_BIH  (SM_HN + 5 * 32)
#define SM_BHH  (SM_BIH + 16)
#define SM_FCW  (SM_BHH + 16)
#define SM6_FLOATS (SM_FCW + 8)                 // 53448 floats = 213,792 B

typedef unsigned long long ull;

// one k-iteration: 4 dup + 16 FFMA2
__device__ __forceinline__ void mv_k(const float* __restrict__ hp,
                                     const float* __restrict__ wp,
                                     ull acc[4][4]) {
    const float4 h0 = *(const float4*)(hp);
    const float4 h1 = *(const float4*)(hp + 4);
    ull hv[4];
    hv[0] = *(const ull*)&h0.x; hv[1] = *(const ull*)&h0.z;
    hv[2] = *(const ull*)&h1.x; hv[3] = *(const ull*)&h1.z;
    const float4 w = *(const float4*)(wp);
    ull wd;
    wd = dup2(w.x);
    acc[0][0]=ffma2(hv[0],wd,acc[0][0]); acc[0][1]=ffma2(hv[1],wd,acc[0][1]);
    acc[0][2]=ffma2(hv[2],wd,acc[0][2]); acc[0][3]=ffma2(hv[3],wd,acc[0][3]);
    wd = dup2(w.y);
    acc[1][0]=ffma2(hv[0],wd,acc[1][0]); acc[1][1]=ffma2(hv[1],wd,acc[1][1]);
    acc[1][2]=ffma2(hv[2],wd,acc[1][2]); acc[1][3]=ffma2(hv[3],wd,acc[1][3]);
    wd = dup2(w.z);
    acc[2][0]=ffma2(hv[0],wd,acc[2][0]); acc[2][1]=ffma2(hv[1],wd,acc[2][1]);
    acc[2][2]=ffma2(hv[2],wd,acc[2][2]); acc[2][3]=ffma2(hv[3],wd,acc[2][3]);
    wd = dup2(w.w);
    acc[3][0]=ffma2(hv[0],wd,acc[3][0]); acc[3][1]=ffma2(hv[1],wd,acc[3][1]);
    acc[3][2]=ffma2(hv[2],wd,acc[3][2]); acc[3][3]=ffma2(hv[3],wd,acc[3][3]);
}

// reduce over kq (lane bits 2..4) and store to accbuf (per-kh partials)
__device__ __forceinline__ void mv_reduce_store(ull acc[4][4],
                                                float* __restrict__ accbuf,
                                                int rg, int kh, int lane) {
#pragma unroll
    for (int r = 0; r < 4; ++r) {
#pragma unroll
        for (int p = 0; p < 4; ++p) {
            float2 f = *(float2*)&acc[r][p];
            f.x += __shfl_xor_sync(0xffffffffu, f.x, 4);
            f.y += __shfl_xor_sync(0xffffffffu, f.y, 4);
            f.x += __shfl_xor_sync(0xffffffffu, f.x, 8);
            f.y += __shfl_xor_sync(0xffffffffu, f.y, 8);
            f.x += __shfl_xor_sync(0xffffffffu, f.x, 16);
            f.y += __shfl_xor_sync(0xffffffffu, f.y, 16);
            *(float2*)&acc[r][p] = f;
        }
    }
    if (lane < 4) {
        const int bg = lane;
#pragma unroll
        for (int r = 0; r < 4; ++r) {
            float* dst = &accbuf[(kh * 16 + rg * 4 + r) * 32 + 8 * bg];
            float2 a0 = *(float2*)&acc[r][0];
            float2 a1 = *(float2*)&acc[r][1];
            float2 a2 = *(float2*)&acc[r][2];
            float2 a3 = *(float2*)&acc[r][3];
            float4 o0; o0.x = a0.x; o0.y = a0.y; o0.z = a1.x; o0.w = a1.y;
            float4 o1; o1.x = a2.x; o1.y = a2.y; o1.z = a3.x; o1.w = a3.y;
            *(float4*)(dst) = o0;
            *(float4*)(dst + 4) = o1;
        }
    }
}

__global__ void __launch_bounds__(256, 1)
k6_gru(const float* __restrict__ W_ih, const float* __restrict__ W_hh,
       const float* __restrict__ b_ih, const float* __restrict__ b_hh,
       const float* __restrict__ fc_w) {
    extern __shared__ float sm[];
    float* sbuf = sm + SM_SBUF;
    float* hb0  = sm + SM_HB;
    float* hb1  = sm + SM_HB + 160 * 32;
    float* wih  = sm + SM_WIH;
    float* whh  = sm + SM_WHH;
    float* xacc = sm + SM_XACC;
    float* gacc = sm + SM_GACC;
    float* hn   = sm + SM_HN;
    float* bih  = sm + SM_BIH;
    float* bhh  = sm + SM_BHH;
    float* fcw  = sm + SM_FCW;

    const int tid = threadIdx.x;
    const int bid = blockIdx.x;
    const int j0 = bid * 5;
    const int wid = tid >> 5;
    const int lane = tid & 31;
    const int rg = wid & 3;          // rows 4rg..+3
    const int kh = wid >> 2;         // 0..1
    const int bg = lane & 3;         // batches 8bg..+7
    const int kq = lane >> 2;        // 0..7
    const int ks = kh * 8 + kq;      // 0..15

    uint32_t sbuf_a = (uint32_t)__cvta_generic_to_shared(sbuf);
    uint32_t hb_a[2] = { (uint32_t)__cvta_generic_to_shared(hb0),
                         (uint32_t)__cvta_generic_to_shared(hb1) };

    // stage weight rows transposed [k][16] (row 15 = zero dummy)
    for (int idx = tid; idx < HDIM * 16; idx += 256) {
        int k = idx >> 4, r = idx & 15;
        float vi = 0.f, vh = 0.f;
        if (r < 15) {
            int grow = (r / 5) * HDIM + j0 + (r % 5);
            vi = W_ih[(size_t)grow * HDIM + k];
            vh = W_hh[(size_t)grow * HDIM + k];
        }
        wih[idx] = vi;
        whh[idx] = vh;
    }
    if (tid < 15) {
        int grow = (tid / 5) * HDIM + j0 + (tid % 5);
        bih[tid] = b_ih[grow];
        bhh[tid] = b_hh[grow];
    }
    if (tid < 5) fcw[tid] = fc_w[j0 + tid];
    for (int i = tid; i < 5 * BATCH; i += 256)
        d_hbuf[0][(j0 + (i >> 5)) * BATCH + (i & 31)] = 0.f;

    // prefetch seq[0] into sbuf
    {
        const float4* src = (const float4*)d_seq;
#pragma unroll
        for (int i = 0; i < 20; ++i)
            cp16(sbuf_a + (tid + 256 * i) * 16, src + tid + 256 * i);
        CP_COMMIT();
    }
    grid_barrier();

    const int pc = tid >> 5;
    const int pb = tid & 31;
    const bool pw = (tid < 160);

    for (int t = 0; t < T_LEN; ++t) {
        CP_WAIT(0);
        __syncthreads();                       // sbuf = seq[t] ready
        unsigned ep = barrier_arrive();        // release h[t] writes from prev iter

        // ---- ih matvec (h-independent; hides barrier latency) ----
        {
            ull acc[4][4];
#pragma unroll
            for (int r = 0; r < 4; ++r)
#pragma unroll
                for (int p = 0; p < 4; ++p) acc[r][p] = 0ull;
            const float* hp = sbuf + (size_t)(ks * 40) * 32 + 8 * bg;
            const float* wp = wih + (size_t)(ks * 40) * 16 + 4 * rg;
#pragma unroll 8
            for (int kk = 0; kk < 40; ++kk)
                mv_k(hp + kk * 32, wp + kk * 16, acc);
            mv_reduce_store(acc, xacc, rg, kh, lane);
        }
        barrier_wait(ep);                      // h[t] globally ready

        float hold = 0.f;
        if (pw) hold = __ldcg(&d_hbuf[t & 1][(j0 + pc) * BATCH + pb]);

        const float* hsrc = d_hbuf[t & 1];
        // pipeline h chunks (4 x 160 k), double-buffered
        {
            const float4* s0 = (const float4*)(hsrc);
#pragma unroll
            for (int i = 0; i < 5; ++i) cp16(hb_a[0] + (tid + 256 * i) * 16, s0 + tid + 256 * i);
            CP_COMMIT();
            const float4* s1 = (const float4*)(hsrc + 160 * 32);
#pragma unroll
            for (int i = 0; i < 5; ++i) cp16(hb_a[1] + (tid + 256 * i) * 16, s1 + tid + 256 * i);
            CP_COMMIT();
        }
        ull acc[4][4];
#pragma unroll
        for (int r = 0; r < 4; ++r)
#pragma unroll
            for (int p = 0; p < 4; ++p) acc[r][p] = 0ull;
        const int koff = ks * 10;              // thread's 10-k slice within each 160-k chunk

        CP_WAIT(1); __syncthreads();
        {
            const float* hp = hb0 + (size_t)koff * 32 + 8 * bg;
            const float* wp = whh + (size_t)(0 * 160 + koff) * 16 + 4 * rg;
#pragma unroll
            for (int kk = 0; kk < 10; ++kk) mv_k(hp + kk * 32, wp + kk * 16, acc);
        }
        __syncthreads();
        {
            const float4* s2 = (const float4*)(hsrc + 2 * 160 * 32);
#pragma unroll
            for (int i = 0; i < 5; ++i) cp16(hb_a[0] + (tid + 256 * i) * 16, s2 + tid + 256 * i);
            CP_COMMIT();
        }
        CP_WAIT(1); __syncthreads();
        {
            const float* hp = hb1 + (size_t)koff * 32 + 8 * bg;
            const float* wp = whh + (size_t)(1 * 160 + koff) * 16 + 4 * rg;
#pragma unroll
            for (int kk = 0; kk < 10; ++kk) mv_k(hp + kk * 32, wp + kk * 16, acc);
        }
        __syncthreads();
        {
            const float4* s3 = (const float4*)(hsrc + 3 * 160 * 32);
#pragma unroll
            for (int i = 0; i < 5; ++i) cp16(hb_a[1] + (tid + 256 * i) * 16, s3 + tid + 256 * i);
            CP_COMMIT();
        }
        CP_WAIT(1); __syncthreads();
        {
            const float* hp = hb0 + (size_t)koff * 32 + 8 * bg;
            const float* wp = whh + (size_t)(2 * 160 + koff) * 16 + 4 * rg;
#pragma unroll
            for (int kk = 0; kk < 10; ++kk) mv_k(hp + kk * 32, wp + kk * 16, acc);
        }
        CP_WAIT(0); __syncthreads();
        {
            const float* hp = hb1 + (size_t)koff * 32 + 8 * bg;
            const float* wp = whh + (size_t)(3 * 160 + koff) * 16 + 4 * rg;
#pragma unroll
            for (int kk = 0; kk < 10; ++kk) mv_k(hp + kk * 32, wp + kk * 16, acc);
        }
        mv_reduce_store(acc, gacc, rg, kh, lane);
        __syncthreads();

        // ---- pointwise GRU cell: 5 units x 32 batch ----
        if (pw) {
            int rr = pc, rz = 5 + pc, rn = 10 + pc;
            float xpr = xacc[rr*32+pb] + xacc[512+rr*32+pb] + bih[rr];
            float xpz = xacc[rz*32+pb] + xacc[512+rz*32+pb] + bih[rz];
            float xpn = xacc[rn*32+pb] + xacc[512+rn*32+pb] + bih[rn];
            float ghr = gacc[rr*32+pb] + gacc[512+rr*32+pb] + bhh[rr];
            float ghz = gacc[rz*32+pb] + gacc[512+rz*32+pb] + bhh[rz];
            float ghn = gacc[rn*32+pb] + gacc[512+rn*32+pb] + bhh[rn];
            float r = 1.f / (1.f + expf(-(xpr + ghr)));
            float z = 1.f / (1.f + expf(-(xpz + ghz)));
            float n = tanhf(xpn + r * ghn);
            float hnew = (1.f - z) * n + z * hold;
            __stcg(&d_hbuf[(t + 1) & 1][(j0 + pc) * BATCH + pb], hnew);
            hn[pc * 32 + pb] = hnew;
        }
        __syncthreads();
        if (tid < 32) {
            float fp = 0.f;
#pragma unroll
            for (int c = 0; c < 5; ++c) fp += hn[c * 32 + tid] * fcw[c];
            d_fcpart[((size_t)t * NB + bid) * 32 + tid] = fp;
        }
        // prefetch seq[t+1]
        if (t + 1 < T_LEN) {
            const float4* src = (const float4*)(d_seq + (size_t)(t + 1) * (HDIM * BATCH));
#pragma unroll
            for (int i = 0; i < 20; ++i)
                cp16(sbuf_a + (tid + 256 * i) * 16, src + tid + 256 * i);
            CP_COMMIT();
        }
    }
}

// ------------------- K7: fc reduction (deterministic) ----------------------
__global__ void k7_out(const float* __restrict__ fc_b, float* __restrict__ out) {
    int t = blockIdx.x;
    int b = threadIdx.x;   // 32 threads
    float s = fc_b[0];
    const float* p = d_fcpart + (size_t)t * NB * 32 + b;
#pragma unroll 16
    for (int i = 0; i < NB; ++i) s += p[i * 32];
    out[(size_t)b * T_LEN + t] = s;
}

// ------------------------- launch ------------------------------------------
extern "C" void kernel_launch(void* const* d_in, const int* in_sizes, int n_in,
                              void* d_out, int out_size) {
    const float* x        = (const float*)d_in[0];
    const float* a_vals   = (const float*)d_in[1];
    const float* w_vals   = (const float*)d_in[2];
    const float* dcls_w   = (const float*)d_in[3];
    const float* dcls_p   = (const float*)d_in[4];
    const float* dcls_b   = (const float*)d_in[5];
    const float* bn_gamma = (const float*)d_in[6];
    const float* bn_beta  = (const float*)d_in[7];
    const float* W_ih     = (const float*)d_in[8];
    const float* W_hh     = (const float*)d_in[9];
    const float* b_ih     = (const float*)d_in[10];
    const float* b_hh     = (const float*)d_in[11];
    const float* fc_w     = (const float*)d_in[12];
    const float* fc_b     = (const float*)d_in[13];
    float* out = (float*)d_out;

    cudaFuncSetAttribute(k3_dcls, cudaFuncAttributeMaxDynamicSharedMemorySize,
                         14 * 1012 * (int)sizeof(float));
    cudaFuncSetAttribute(k6_gru, cudaFuncAttributeMaxDynamicSharedMemorySize,
                         SM6_FLOATS * (int)sizeof(float));

    k1_highpass<<<dim3(BATCH, NF), 256>>>(x, a_vals, w_vals);
    k2_dk<<<(HDIM * 14 + 255) / 256, 256>>>(dcls_w, dcls_p);
    k3_dcls<<<dim3(10, BATCH), 256, 14 * 1012 * sizeof(float)>>>(dcls_b);
    k4a_stats<<<640, 256>>>();
    k4b_stats<<<1, 64>>>();
    k5_norm<<<HDIM, 256>>>(bn_gamma, bn_beta);
    k6_gru<<<NB, 256, SM6_FLOATS * sizeof(float)>>>(W_ih, W_hh, b_ih, b_hh, fc_w);
    k7_out<<<T_LEN, 32>>>(fc_b, out);
}

// round 16
// speedup vs baseline: 1.5213x; 1.5213x over previous
#include <cuda_runtime.h>
#include <math.h>
#include <stdint.h>

#define T_LEN 1000
#define BATCH 32
#define NF 34
#define HDIM 640
#define NB 128            // persistent blocks (5 hidden cols each)

// ------------------------- device scratch ----------------------------------
__device__ float d_X2[BATCH * 2 * NF * T_LEN];           // 8.7 MB
__device__ float d_dkw0[HDIM * 14];
__device__ float d_dkw1[HDIM * 14];
__device__ int   d_dklo[HDIM * 14];
__device__ float d_Y[HDIM * BATCH * T_LEN];              // 81.9 MB  [hseq][b][t]
__device__ double d_p4sum[640];
__device__ double d_p4sq[640];
__device__ float d_mean[64];
__device__ float d_rstd[64];
__device__ float d_seq[(size_t)T_LEN * HDIM * BATCH];    // 81.9 MB  [t][k][b]
__device__ float d_hbuf[2][HDIM * BATCH];                // ping-pong h  [k][b]
__device__ float d_fcpart[(size_t)T_LEN * NB * BATCH];   // 16.4 MB

// ------------------------- grid barrier ------------------------------------
__device__ volatile unsigned g_epoch = 0;
__device__ unsigned g_count = 0;

__device__ __forceinline__ void grid_barrier() {
    __syncthreads();
    if (threadIdx.x == 0) {
        unsigned e = g_epoch;
        __threadfence();
        if (atomicAdd(&g_count, 1u) == NB - 1) {
            g_count = 0;
            __threadfence();
            g_epoch = e + 1;
        } else {
            while (g_epoch == e) { }
        }
        __threadfence();
    }
    __syncthreads();
}

__device__ __forceinline__ unsigned barrier_arrive() {
    unsigned e = 0;
    __syncthreads();
    if (threadIdx.x == 0) {
        e = g_epoch;
        __threadfence();
        if (atomicAdd(&g_count, 1u) == NB - 1) {
            g_count = 0;
            __threadfence();
            g_epoch = e + 1;
        }
    }
    return e;
}
__device__ __forceinline__ void barrier_wait(unsigned e) {
    if (threadIdx.x == 0) {
        while (g_epoch == e) { }
        __threadfence();
    }
    __syncthreads();
}

// ------------------------- f32x2 / cp.async helpers ------------------------
typedef unsigned long long ull;

__device__ __forceinline__ ull ffma2(ull a, ull b, ull c) {
    ull d;
    asm("fma.rn.f32x2 %0, %1, %2, %3;" : "=l"(d) : "l"(a), "l"(b), "l"(c));
    return d;
}
__device__ __forceinline__ ull dup2(float w) {
    ull d;
    asm("mov.b64 %0, {%1, %1};" : "=l"(d) : "r"(__float_as_uint(w)));
    return d;
}
__device__ __forceinline__ void cp16(uint32_t dst, const void* src) {
    asm volatile("cp.async.cg.shared.global [%0], [%1], 16;" :: "r"(dst), "l"(src));
}
#define CP_COMMIT() asm volatile("cp.async.commit_group;")
#define CP_WAIT(N)  asm volatile("cp.async.wait_group %0;" :: "n"(N))

// ------------------- K1: truncated EMA highpass + rectify ------------------
__global__ void k1_highpass(const float* __restrict__ x,
                            const float* __restrict__ a_vals,
                            const float* __restrict__ w_vals) {
    int b = blockIdx.x, f = blockIdx.y;
    __shared__ float xs[T_LEN];
    __shared__ float cs[200];
    const float* xr = x + (size_t)(b * NF + f) * T_LEN;
    for (int i = threadIdx.x; i < T_LEN; i += 256) xs[i] = xr[i];
    float a = a_vals[f];
    float w = w_vals[f];
    float l2 = log2f(1.0f - a);
    for (int j = threadIdx.x; j < 200; j += 256) cs[j] = a * exp2f(l2 * (float)j);
    __syncthreads();
    for (int t = threadIdx.x; t < T_LEN; t += 256) {
        float low = 0.f;
        int jm = min(199, t);
        for (int j = 0; j <= jm; ++j) low += cs[j] * xs[t - j];
        float hp = xs[t] - w * low;
        d_X2[((size_t)(b * 2 + 0) * NF + f) * T_LEN + t] = fmaxf(hp, 0.f);
        d_X2[((size_t)(b * 2 + 1) * NF + f) * T_LEN + t] = fmaxf(-hp, 0.f);
    }
}

// ------------------- K2: DCLS triangular kernel -> 2 taps ------------------
__global__ void k2_dk(const float* __restrict__ dcls_w,
                      const float* __restrict__ dcls_p) {
    int idx = blockIdx.x * 256 + threadIdx.x;
    if (idx < HDIM * 14) {
        float p = fminf(fmaxf(dcls_p[idx], 0.f), 8.f);
        float lo = floorf(p);
        float fr = p - lo;
        float w = dcls_w[idx];
        d_dkw0[idx] = w * (1.f - fr);
        d_dkw1[idx] = w * fr;
        d_dklo[idx] = (int)lo;
    }
}

// ------------------- K3: DCLS grouped conv + bias --------------------------
__global__ void k3_dcls(const float* __restrict__ dcls_b) {
    int g = blockIdx.x;     // 0..9
    int b = blockIdx.y;     // 0..31
    extern __shared__ float us[];           // 14 * 1012 floats
    const int P = 1012;
    for (int i = threadIdx.x; i < 14 * P; i += 256) us[i] = 0.f;
    __syncthreads();
    for (int i = 0; i < 14; ++i) {
        int s = i / 7, kk = i % 7;
        const float* src = d_X2 + ((size_t)(b * 2 + s) * NF + g * 3 + kk) * T_LEN;
        for (int t = threadIdx.x; t < T_LEN; t += 256) us[i * P + 4 + t] = src[t];
    }
    __syncthreads();
    for (int c = 0; c < 64; ++c) {
        int h = g * 64 + c;
        float w0[14], w1[14]; int lo[14];
#pragma unroll
        for (int i = 0; i < 14; ++i) {
            w0[i] = d_dkw0[h * 14 + i];
            w1[i] = d_dkw1[h * 14 + i];
            lo[i] = d_dklo[h * 14 + i];
        }
        float bias = dcls_b[h];
        int hseq = c * 10 + g;
        float* dst = d_Y + ((size_t)hseq * BATCH + b) * T_LEN;
        for (int t = threadIdx.x; t < T_LEN; t += 256) {
            float acc = bias;
#pragma unroll
            for (int i = 0; i < 14; ++i) {
                acc += w0[i] * us[i * P + t + lo[i]];
                acc += w1[i] * us[i * P + t + lo[i] + 1];
            }
            dst[t] = acc;
        }
    }
}

// ------------------- K4a: BN partial sums (640 blocks, 256 thr) ------------
__global__ void k4a_stats() {
    const int bid = blockIdx.x;
    const float4* p = (const float4*)(d_Y + (size_t)bid * 32000);
    double s0 = 0.0, s1 = 0.0, q0 = 0.0, q1 = 0.0;
    for (int i = threadIdx.x; i < 8000; i += 512) {
        float4 v = p[i];
        s0 += (double)v.x + (double)v.y;
        s1 += (double)v.z + (double)v.w;
        q0 += (double)v.x * v.x + (double)v.y * v.y;
        q1 += (double)v.z * v.z + (double)v.w * v.w;
        int i2 = i + 256;
        if (i2 < 8000) {
            float4 u = p[i2];
            s0 += (double)u.x + (double)u.y;
            s1 += (double)u.z + (double)u.w;
            q0 += (double)u.x * u.x + (double)u.y * u.y;
            q1 += (double)u.z * u.z + (double)u.w * u.w;
        }
    }
    double s = s0 + s1, s2 = q0 + q1;
    __shared__ double sh[256], sh2[256];
    sh[threadIdx.x] = s; sh2[threadIdx.x] = s2;
    __syncthreads();
    for (int o = 128; o > 0; o >>= 1) {
        if (threadIdx.x < o) { sh[threadIdx.x] += sh[threadIdx.x + o]; sh2[threadIdx.x] += sh2[threadIdx.x + o]; }
        __syncthreads();
    }
    if (threadIdx.x == 0) { d_p4sum[bid] = sh[0]; d_p4sq[bid] = sh2[0]; }
}

// ------------------- K4b: combine -> mean/rstd -----------------------------
__global__ void k4b_stats() {
    int c = threadIdx.x;                    // 64 threads
    double s = 0.0, s2 = 0.0;
#pragma unroll
    for (int j = 0; j < 10; ++j) { s += d_p4sum[c * 10 + j]; s2 += d_p4sq[c * 10 + j]; }
    double mean = s / 320000.0;
    double var = s2 / 320000.0 - mean * mean;
    d_mean[c] = (float)mean;
    d_rstd[c] = (float)(1.0 / sqrt(var + 1e-5));
}

// ------------------- K5: normalize + sigmoid -> seq[t][k][b] ---------------
__global__ void k5_norm(const float* __restrict__ gamma,
                        const float* __restrict__ beta) {
    int h = blockIdx.x;
    int c = h / 10;
    float m = d_mean[c], r = d_rstd[c], ga = gamma[c], be = beta[c];
    const float* src = d_Y + (size_t)h * BATCH * T_LEN;
    __shared__ float ts[32][257];
    for (int t0 = 0; t0 < T_LEN; t0 += 256) {
        __syncthreads();
        for (int i = threadIdx.x; i < 32 * 256; i += 256) {
            int b = i >> 8, tl = i & 255;
            if (t0 + tl < T_LEN) ts[b][tl] = src[(size_t)b * T_LEN + t0 + tl];
        }
        __syncthreads();
        int b2 = threadIdx.x & 31, tl2 = threadIdx.x >> 5;
        for (int tt = tl2; tt < 256 && t0 + tt < T_LEN; tt += 8) {
            float v = (ts[b2][tt] - m) * r * ga + be;
            float sg = 1.f / (1.f + expf(-v));
            d_seq[(size_t)(t0 + tt) * (HDIM * BATCH) + h * BATCH + b2] = sg;
        }
    }
}

// ------------------- K6: persistent GRU (scheme B: dup h, natural w pairs) -
// warp w: rg2 = w&1 -> rows r0=8*rg2..+7; kh = w>>1 (0..3)
// lane l: bq = l&7 -> batches 4bq..+3; kq = l>>3 (0..3); slice ks = kh*4+kq
// Per k-iter: 1x LDS.128 h (4 batches), 2x LDS.128 w (8 rows as 4 pairs,
// broadcast), 4 dup(h), 16 FFMA2 -> acc[rp][b] = {row r0+2rp, r0+2rp+1} @ b.
// acc store layout: accbuf[(((kh*8 + rg2*4 + rp)*4 + b)*8 + bq)*2 + j],
// j = row parity. float2 stores stride 2*bq -> conflict-free.
#define SM_SBUF 0
#define SM_HB   (SM_SBUF + HDIM * BATCH)        // 20480
#define SM_WIH  (SM_HB + 2 * 160 * 32)          // +10240
#define SM_WHH  (SM_WIH + HDIM * 16)            // +10240
#define SM_XACC (SM_WHH + HDIM * 16)            // +10240
#define SM_GACC (SM_XACC + 2048)                // +2048
#define SM_HN   (SM_GACC + 2048)                // +2048
#define SM_BIH  (SM_HN + 5 * 32)
#define SM_BHH  (SM_BIH + 16)
#define SM_FCW  (SM_BHH + 16)
#define SM6_FLOATS (SM_FCW + 8)                 // 55496 floats = 221,984 B

// one k-iteration, scheme B: 4 dup + 16 FFMA2
__device__ __forceinline__ void mv_kB(const float* __restrict__ hp,
                                      const float* __restrict__ wp,
                                      ull acc[4][4]) {
    const float4 h = *(const float4*)(hp);           // 4 batches
    const ulonglong2 w0 = *(const ulonglong2*)(wp);      // row pairs {r0,r0+1},{r0+2,r0+3}
    const ulonglong2 w1 = *(const ulonglong2*)(wp + 4);  // {r0+4,r0+5},{r0+6,r0+7}
    ull hd;
    hd = dup2(h.x);
    acc[0][0]=ffma2(w0.x,hd,acc[0][0]); acc[1][0]=ffma2(w0.y,hd,acc[1][0]);
    acc[2][0]=ffma2(w1.x,hd,acc[2][0]); acc[3][0]=ffma2(w1.y,hd,acc[3][0]);
    hd = dup2(h.y);
    acc[0][1]=ffma2(w0.x,hd,acc[0][1]); acc[1][1]=ffma2(w0.y,hd,acc[1][1]);
    acc[2][1]=ffma2(w1.x,hd,acc[2][1]); acc[3][1]=ffma2(w1.y,hd,acc[3][1]);
    hd = dup2(h.z);
    acc[0][2]=ffma2(w0.x,hd,acc[0][2]); acc[1][2]=ffma2(w0.y,hd,acc[1][2]);
    acc[2][2]=ffma2(w1.x,hd,acc[2][2]); acc[3][2]=ffma2(w1.y,hd,acc[3][2]);
    hd = dup2(h.w);
    acc[0][3]=ffma2(w0.x,hd,acc[0][3]); acc[1][3]=ffma2(w0.y,hd,acc[1][3]);
    acc[2][3]=ffma2(w1.x,hd,acc[2][3]); acc[3][3]=ffma2(w1.y,hd,acc[3][3]);
}

// reduce over kq (lanes xor 8, 16) and store row-pair float2s
__device__ __forceinline__ void mv_reduceB(ull acc[4][4],
                                           float* __restrict__ accbuf,
                                           int rg2, int kh, int lane, int bq) {
#pragma unroll
    for (int rp = 0; rp < 4; ++rp) {
#pragma unroll
        for (int b = 0; b < 4; ++b) {
            float2 f = *(float2*)&acc[rp][b];
            f.x += __shfl_xor_sync(0xffffffffu, f.x, 8);
            f.y += __shfl_xor_sync(0xffffffffu, f.y, 8);
            f.x += __shfl_xor_sync(0xffffffffu, f.x, 16);
            f.y += __shfl_xor_sync(0xffffffffu, f.y, 16);
            *(float2*)&acc[rp][b] = f;
        }
    }
    if (lane < 8) {
#pragma unroll
        for (int rp = 0; rp < 4; ++rp)
#pragma unroll
            for (int b = 0; b < 4; ++b)
                *(float2*)&accbuf[(((kh * 8 + rg2 * 4 + rp) * 4 + b) * 8 + bq) * 2] =
                    *(float2*)&acc[rp][b];
    }
}

// accbuf read index for (kh, row 0..15, batch 0..31)
__device__ __forceinline__ int acc_idx(int kh, int row, int batch) {
    int rg2v = row >> 3, rowin = row & 7, rp = rowin >> 1, j = rowin & 1;
    int b = batch & 3, bq = batch >> 2;
    return (((kh * 8 + rg2v * 4 + rp) * 4 + b) * 8 + bq) * 2 + j;
}

__global__ void __launch_bounds__(256, 1)
k6_gru(const float* __restrict__ W_ih, const float* __restrict__ W_hh,
       const float* __restrict__ b_ih, const float* __restrict__ b_hh,
       const float* __restrict__ fc_w) {
    extern __shared__ float sm[];
    float* sbuf = sm + SM_SBUF;
    float* hb0  = sm + SM_HB;
    float* hb1  = sm + SM_HB + 160 * 32;
    float* wih  = sm + SM_WIH;
    float* whh  = sm + SM_WHH;
    float* xacc = sm + SM_XACC;
    float* gacc = sm + SM_GACC;
    float* hn   = sm + SM_HN;
    float* bih  = sm + SM_BIH;
    float* bhh  = sm + SM_BHH;
    float* fcw  = sm + SM_FCW;

    const int tid = threadIdx.x;
    const int bid = blockIdx.x;
    const int j0 = bid * 5;
    const int wid = tid >> 5;
    const int lane = tid & 31;
    const int rg2 = wid & 1;         // rows r0 = 8*rg2 .. +7
    const int kh = wid >> 1;         // 0..3
    const int bq = lane & 7;         // batches 4bq..+3
    const int kq = lane >> 3;        // 0..3
    const int r0 = rg2 * 8;

    uint32_t sbuf_a = (uint32_t)__cvta_generic_to_shared(sbuf);
    uint32_t hb_a[2] = { (uint32_t)__cvta_generic_to_shared(hb0),
                         (uint32_t)__cvta_generic_to_shared(hb1) };

    // stage weight rows transposed [k][16] (row 15 = zero dummy)
    for (int idx = tid; idx < HDIM * 16; idx += 256) {
        int k = idx >> 4, r = idx & 15;
        float vi = 0.f, vh = 0.f;
        if (r < 15) {
            int grow = (r / 5) * HDIM + j0 + (r % 5);
            vi = W_ih[(size_t)grow * HDIM + k];
            vh = W_hh[(size_t)grow * HDIM + k];
        }
        wih[idx] = vi;
        whh[idx] = vh;
    }
    if (tid < 15) {
        int grow = (tid / 5) * HDIM + j0 + (tid % 5);
        bih[tid] = b_ih[grow];
        bhh[tid] = b_hh[grow];
    }
    if (tid < 5) fcw[tid] = fc_w[j0 + tid];
    for (int i = tid; i < 5 * BATCH; i += 256)
        d_hbuf[0][(j0 + (i >> 5)) * BATCH + (i & 31)] = 0.f;

    // prefetch seq[0] into sbuf
    {
        const float4* src = (const float4*)d_seq;
#pragma unroll
        for (int i = 0; i < 20; ++i)
            cp16(sbuf_a + (tid + 256 * i) * 16, src + tid + 256 * i);
        CP_COMMIT();
    }
    grid_barrier();

    const int pc = tid >> 5;
    const int pb = tid & 31;
    const bool pw = (tid < 160);

    for (int t = 0; t < T_LEN; ++t) {
        CP_WAIT(0);
        __syncthreads();                       // sbuf = seq[t] ready
        unsigned ep = barrier_arrive();        // release h[t] writes from prev iter

        // ---- ih matvec (h-independent; hides barrier latency) ----
        {
            ull acc[4][4];
#pragma unroll
            for (int rp = 0; rp < 4; ++rp)
#pragma unroll
                for (int b = 0; b < 4; ++b) acc[rp][b] = 0ull;
            const int k0 = (kh * 4 + kq) * 40;
            const float* hp = sbuf + (size_t)k0 * 32 + 4 * bq;
            const float* wp = wih + (size_t)k0 * 16 + r0;
#pragma unroll 8
            for (int kk = 0; kk < 40; ++kk)
                mv_kB(hp + kk * 32, wp + kk * 16, acc);
            mv_reduceB(acc, xacc, rg2, kh, lane, bq);
        }
        barrier_wait(ep);                      // h[t] globally ready

        float hold = 0.f;
        if (pw) hold = __ldcg(&d_hbuf[t & 1][(j0 + pc) * BATCH + pb]);

        const float* hsrc = d_hbuf[t & 1];
        // pipeline h chunks (4 x 160 k), double-buffered
        {
            const float4* s0 = (const float4*)(hsrc);
#pragma unroll
            for (int i = 0; i < 5; ++i) cp16(hb_a[0] + (tid + 256 * i) * 16, s0 + tid + 256 * i);
            CP_COMMIT();
            const float4* s1 = (const float4*)(hsrc + 160 * 32);
#pragma unroll
            for (int i = 0; i < 5; ++i) cp16(hb_a[1] + (tid + 256 * i) * 16, s1 + tid + 256 * i);
            CP_COMMIT();
        }
        ull acc[4][4];
#pragma unroll
        for (int rp = 0; rp < 4; ++rp)
#pragma unroll
            for (int b = 0; b < 4; ++b) acc[rp][b] = 0ull;
        const int koff = (kh * 4 + kq) * 10;   // thread's 10-k slice per 160-k chunk

        CP_WAIT(1); __syncthreads();
        {
            const float* hp = hb0 + (size_t)koff * 32 + 4 * bq;
            const float* wp = whh + (size_t)(0 * 160 + koff) * 16 + r0;
#pragma unroll
            for (int kk = 0; kk < 10; ++kk) mv_kB(hp + kk * 32, wp + kk * 16, acc);
        }
        __syncthreads();
        {
            const float4* s2 = (const float4*)(hsrc + 2 * 160 * 32);
#pragma unroll
            for (int i = 0; i < 5; ++i) cp16(hb_a[0] + (tid + 256 * i) * 16, s2 + tid + 256 * i);
            CP_COMMIT();
        }
        CP_WAIT(1); __syncthreads();
        {
            const float* hp = hb1 + (size_t)koff * 32 + 4 * bq;
            const float* wp = whh + (size_t)(1 * 160 + koff) * 16 + r0;
#pragma unroll
            for (int kk = 0; kk < 10; ++kk) mv_kB(hp + kk * 32, wp + kk * 16, acc);
        }
        __syncthreads();
        {
            const float4* s3 = (const float4*)(hsrc + 3 * 160 * 32);
#pragma unroll
            for (int i = 0; i < 5; ++i) cp16(hb_a[1] + (tid + 256 * i) * 16, s3 + tid + 256 * i);
            CP_COMMIT();
        }
        CP_WAIT(1); __syncthreads();
        {
            const float* hp = hb0 + (size_t)koff * 32 + 4 * bq;
            const float* wp = whh + (size_t)(2 * 160 + koff) * 16 + r0;
#pragma unroll
            for (int kk = 0; kk < 10; ++kk) mv_kB(hp + kk * 32, wp + kk * 16, acc);
        }
        CP_WAIT(0); __syncthreads();
        {
            const float* hp = hb1 + (size_t)koff * 32 + 4 * bq;
            const float* wp = whh + (size_t)(3 * 160 + koff) * 16 + r0;
#pragma unroll
            for (int kk = 0; kk < 10; ++kk) mv_kB(hp + kk * 32, wp + kk * 16, acc);
        }
        mv_reduceB(acc, gacc, rg2, kh, lane, bq);
        __syncthreads();

        // ---- pointwise GRU cell: 5 units x 32 batch ----
        if (pw) {
            int rr = pc, rz = 5 + pc, rn = 10 + pc;
            float xpr = xacc[acc_idx(0, rr, pb)] + xacc[acc_idx(1, rr, pb)]
                      + xacc[acc_idx(2, rr, pb)] + xacc[acc_idx(3, rr, pb)] + bih[rr];
            float xpz = xacc[acc_idx(0, rz, pb)] + xacc[acc_idx(1, rz, pb)]
                      + xacc[acc_idx(2, rz, pb)] + xacc[acc_idx(3, rz, pb)] + bih[rz];
            float xpn = xacc[acc_idx(0, rn, pb)] + xacc[acc_idx(1, rn, pb)]
                      + xacc[acc_idx(2, rn, pb)] + xacc[acc_idx(3, rn, pb)] + bih[rn];
            float ghr = gacc[acc_idx(0, rr, pb)] + gacc[acc_idx(1, rr, pb)]
                      + gacc[acc_idx(2, rr, pb)] + gacc[acc_idx(3, rr, pb)] + bhh[rr];
            float ghz = gacc[acc_idx(0, rz, pb)] + gacc[acc_idx(1, rz, pb)]
                      + gacc[acc_idx(2, rz, pb)] + gacc[acc_idx(3, rz, pb)] + bhh[rz];
            float ghn = gacc[acc_idx(0, rn, pb)] + gacc[acc_idx(1, rn, pb)]
                      + gacc[acc_idx(2, rn, pb)] + gacc[acc_idx(3, rn, pb)] + bhh[rn];
            float r = 1.f / (1.f + expf(-(xpr + ghr)));
            float z = 1.f / (1.f + expf(-(xpz + ghz)));
            float n = tanhf(xpn + r * ghn);
            float hnew = (1.f - z) * n + z * hold;
            __stcg(&d_hbuf[(t + 1) & 1][(j0 + pc) * BATCH + pb], hnew);
            hn[pc * 32 + pb] = hnew;
        }
        __syncthreads();
        if (tid < 32) {
            float fp = 0.f;
#pragma unroll
            for (int c = 0; c < 5; ++c) fp += hn[c * 32 + tid] * fcw[c];
            d_fcpart[((size_t)t * NB + bid) * 32 + tid] = fp;
        }
        // prefetch seq[t+1]
        if (t + 1 < T_LEN) {
            const float4* src = (const float4*)(d_seq + (size_t)(t + 1) * (HDIM * BATCH));
#pragma unroll
            for (int i = 0; i < 20; ++i)
                cp16(sbuf_a + (tid + 256 * i) * 16, src + tid + 256 * i);
            CP_COMMIT();
        }
    }
}

// ------------------- K7: fc reduction (deterministic) ----------------------
__global__ void k7_out(const float* __restrict__ fc_b, float* __restrict__ out) {
    int t = blockIdx.x;
    int b = threadIdx.x;   // 32 threads
    float s = fc_b[0];
    const float* p = d_fcpart + (size_t)t * NB * 32 + b;
#pragma unroll 16
    for (int i = 0; i < NB; ++i) s += p[i * 32];
    out[(size_t)b * T_LEN + t] = s;
}

// ------------------------- launch ------------------------------------------
extern "C" void kernel_launch(void* const* d_in, const int* in_sizes, int n_in,
                              void* d_out, int out_size) {
    const float* x        = (const float*)d_in[0];
    const float* a_vals   = (const float*)d_in[1];
    const float* w_vals   = (const float*)d_in[2];
    const float* dcls_w   = (const float*)d_in[3];
    const float* dcls_p   = (const float*)d_in[4];
    const float* dcls_b   = (const float*)d_in[5];
    const float* bn_gamma = (const float*)d_in[6];
    const float* bn_beta  = (const float*)d_in[7];
    const float* W_ih     = (const float*)d_in[8];
    const float* W_hh     = (const float*)d_in[9];
    const float* b_ih     = (const float*)d_in[10];
    const float* b_hh     = (const float*)d_in[11];
    const float* fc_w     = (const float*)d_in[12];
    const float* fc_b     = (const float*)d_in[13];
    float* out = (float*)d_out;

    cudaFuncSetAttribute(k3_dcls, cudaFuncAttributeMaxDynamicSharedMemorySize,
                         14 * 1012 * (int)sizeof(float));
    cudaFuncSetAttribute(k6_gru, cudaFuncAttributeMaxDynamicSharedMemorySize,
                         SM6_FLOATS * (int)sizeof(float));

    k1_highpass<<<dim3(BATCH, NF), 256>>>(x, a_vals, w_vals);
    k2_dk<<<(HDIM * 14 + 255) / 256, 256>>>(dcls_w, dcls_p);
    k3_dcls<<<dim3(10, BATCH), 256, 14 * 1012 * sizeof(float)>>>(dcls_b);
    k4a_stats<<<640, 256>>>();
    k4b_stats<<<1, 64>>>();
    k5_norm<<<HDIM, 256>>>(bn_gamma, bn_beta);
    k6_gru<<<NB, 256, SM6_FLOATS * sizeof(float)>>>(W_ih, W_hh, b_ih, b_hh, fc_w);
    k7_out<<<T_LEN, 32>>>(fc_b, out);
}